// round 2
// baseline (speedup 1.0000x reference)
#include <cuda_runtime.h>

// SelfAttn: B=16, C=64, H=W=64. theta/phi: C/8=8 ch, g: C/2=32 ch.
// phi,g maxpooled 2x2 -> M=1024 keys. HW=4096 queries.

#define BATCH 16
#define CDIM  64
#define HWDIM 4096
#define MDIM  1024
#define CT    8      // theta/phi channels
#define CG    32     // g channels

// Scratch (allocation-free rule: __device__ globals)
__device__ float d_theta[BATCH * HWDIM * CT];   // [b][n][8]
__device__ float d_phi  [BATCH * MDIM  * CT];   // [b][m][8]
__device__ float d_gbuf [BATCH * MDIM  * CG];   // [b][m][32]

// ---------------------------------------------------------------------------
// Kernel A: 1x1 projections + fused 2x2 maxpool for phi/g.
// One thread per pooled pixel (handles its 2x2 raw-pixel block).
// grid (8, 16), block 128.
// ---------------------------------------------------------------------------
__global__ __launch_bounds__(128) void proj_kernel(
    const float* __restrict__ x,
    const float* __restrict__ wt,
    const float* __restrict__ wp,
    const float* __restrict__ wg)
{
    __shared__ float s_wt[CT * CDIM];
    __shared__ float s_wp[CT * CDIM];
    __shared__ float s_wg[CG * CDIM];
    int tid = threadIdx.x;
    for (int i = tid; i < CT * CDIM; i += 128) { s_wt[i] = wt[i]; s_wp[i] = wp[i]; }
    for (int i = tid; i < CG * CDIM; i += 128) s_wg[i] = wg[i];
    __syncthreads();

    int b  = blockIdx.y;
    int pp = blockIdx.x * 128 + tid;       // pooled pixel 0..1023
    int py = pp >> 5, px = pp & 31;
    const float* xb = x + (size_t)b * CDIM * HWDIM;

    float phi_acc[CT], g_acc[CG];
#pragma unroll
    for (int o = 0; o < CT; o++) phi_acc[o] = -3.0e38f;
#pragma unroll
    for (int o = 0; o < CG; o++) g_acc[o] = -3.0e38f;

#pragma unroll
    for (int d = 0; d < 4; d++) {
        int dy = d >> 1, dx = d & 1;
        int pix = (2 * py + dy) * 64 + (2 * px + dx);
        float th[CT], phv[CT], gv[CG];
#pragma unroll
        for (int o = 0; o < CT; o++) { th[o] = 0.f; phv[o] = 0.f; }
#pragma unroll
        for (int o = 0; o < CG; o++) gv[o] = 0.f;

        for (int c = 0; c < CDIM; c++) {
            float xc = xb[(size_t)c * HWDIM + pix];
#pragma unroll
            for (int o = 0; o < CT; o++) {
                th[o]  = fmaf(s_wt[o * CDIM + c], xc, th[o]);
                phv[o] = fmaf(s_wp[o * CDIM + c], xc, phv[o]);
            }
#pragma unroll
            for (int o = 0; o < CG; o++)
                gv[o] = fmaf(s_wg[o * CDIM + c], xc, gv[o]);
        }

        float* tp = &d_theta[((size_t)b * HWDIM + pix) * CT];
#pragma unroll
        for (int o = 0; o < CT; o++) tp[o] = th[o];
#pragma unroll
        for (int o = 0; o < CT; o++) phi_acc[o] = fmaxf(phi_acc[o], phv[o]);
#pragma unroll
        for (int o = 0; o < CG; o++) g_acc[o] = fmaxf(g_acc[o], gv[o]);
    }

    float* pph = &d_phi[((size_t)b * MDIM + pp) * CT];
#pragma unroll
    for (int o = 0; o < CT; o++) pph[o] = phi_acc[o];
    float* pg = &d_gbuf[((size_t)b * MDIM + pp) * CG];
#pragma unroll
    for (int o = 0; o < CG; o++) pg[o] = g_acc[o];
}

// ---------------------------------------------------------------------------
// Kernel B: fused attention + output projection + residual.
// CTA = (256-query tile, batch). phi + g + w_o resident in smem (168 KB).
// One thread per query; all smem reads inside the m-loop are warp-broadcasts.
// Single-pass softmax (scores bounded ~|20| << 88, shift by const 12).
// ---------------------------------------------------------------------------
__global__ __launch_bounds__(256, 1) void attn_kernel(
    const float* __restrict__ x,
    const float* __restrict__ wo,
    const float* __restrict__ gamma,
    float* __restrict__ out)
{
    extern __shared__ float smem[];
    float* s_phi = smem;                    // [M][8]
    float* s_g   = smem + MDIM * CT;        // [M][32]
    float* s_wo  = s_g + MDIM * CG;         // [64][32]

    int tid = threadIdx.x;
    int b   = blockIdx.y;

    {   // cooperative smem fill (float4)
        const float4* sp = (const float4*)&d_phi[(size_t)b * MDIM * CT];
        float4* dp = (float4*)s_phi;
        for (int i = tid; i < MDIM * CT / 4; i += 256) dp[i] = sp[i];
        const float4* sg = (const float4*)&d_gbuf[(size_t)b * MDIM * CG];
        float4* dg = (float4*)s_g;
        for (int i = tid; i < MDIM * CG / 4; i += 256) dg[i] = sg[i];
        const float4* sw = (const float4*)wo;
        float4* dw = (float4*)s_wo;
        for (int i = tid; i < CDIM * CG / 4; i += 256) dw[i] = sw[i];
    }
    __syncthreads();

    int n = blockIdx.x * 256 + tid;
    const float4* thp = (const float4*)&d_theta[((size_t)b * HWDIM + n) * CT];
    float4 t0 = thp[0];
    float4 t1 = thp[1];

    float sum = 0.0f;
    float acc[CG];
#pragma unroll
    for (int k = 0; k < CG; k++) acc[k] = 0.0f;

#pragma unroll 4
    for (int m = 0; m < MDIM; m++) {
        const float4* pp = (const float4*)&s_phi[m * CT];
        float4 p0 = pp[0], p1 = pp[1];
        float s = -12.0f;                    // fixed shift; cancels in normalization
        s = fmaf(t0.x, p0.x, s); s = fmaf(t0.y, p0.y, s);
        s = fmaf(t0.z, p0.z, s); s = fmaf(t0.w, p0.w, s);
        s = fmaf(t1.x, p1.x, s); s = fmaf(t1.y, p1.y, s);
        s = fmaf(t1.z, p1.z, s); s = fmaf(t1.w, p1.w, s);
        float e = __expf(s);
        sum += e;
        const float4* gp = (const float4*)&s_g[m * CG];
#pragma unroll
        for (int q = 0; q < 8; q++) {
            float4 gv = gp[q];
            acc[4 * q + 0] = fmaf(e, gv.x, acc[4 * q + 0]);
            acc[4 * q + 1] = fmaf(e, gv.y, acc[4 * q + 1]);
            acc[4 * q + 2] = fmaf(e, gv.z, acc[4 * q + 2]);
            acc[4 * q + 3] = fmaf(e, gv.w, acc[4 * q + 3]);
        }
    }

    float inv = 1.0f / sum;
#pragma unroll
    for (int k = 0; k < CG; k++) acc[k] *= inv;

    float gm = *gamma;
    const float* xb = x   + (size_t)b * CDIM * HWDIM + n;
    float*       ob = out + (size_t)b * CDIM * HWDIM + n;
#pragma unroll
    for (int c = 0; c < CDIM; c++) {
        const float* wr = &s_wo[c * CG];
        float v = 0.0f;
#pragma unroll
        for (int k = 0; k < CG; k++) v = fmaf(wr[k], acc[k], v);
        ob[(size_t)c * HWDIM] = fmaf(gm, v, xb[(size_t)c * HWDIM]);
    }
}

// ---------------------------------------------------------------------------
extern "C" void kernel_launch(void* const* d_in, const int* in_sizes, int n_in,
                              void* d_out, int out_size)
{
    const float* x  = (const float*)d_in[0];
    const float* wt = (const float*)d_in[1];
    const float* wp = (const float*)d_in[2];
    const float* wg = (const float*)d_in[3];
    const float* wo = (const float*)d_in[4];
    const float* gm = (const float*)d_in[5];
    float* out = (float*)d_out;

    proj_kernel<<<dim3(8, BATCH), 128>>>(x, wt, wp, wg);

    int smem_bytes = (MDIM * CT + MDIM * CG + CDIM * CG) * (int)sizeof(float); // 172032
    cudaFuncSetAttribute(attn_kernel, cudaFuncAttributeMaxDynamicSharedMemorySize,
                         smem_bytes);
    attn_kernel<<<dim3(HWDIM / 256, BATCH), 256, smem_bytes>>>(x, wo, gm, out);
}

// round 3
// speedup vs baseline: 1.2391x; 1.2391x over previous
#include <cuda_runtime.h>

// SelfAttn: B=16, C=64, H=W=64. theta/phi: 8 ch, g: 32 ch.
// phi,g maxpooled 2x2 -> M=1024 keys. HW=4096 queries.

#define BATCH 16
#define CDIM  64
#define HWDIM 4096
#define MDIM  1024
#define CT    8
#define CG    32
#define MSPLIT 2
#define MHALF (MDIM / MSPLIT)   // 512

typedef unsigned long long u64;

__device__ __forceinline__ u64 pack2(float lo, float hi) {
    u64 r; asm("mov.b64 %0, {%1,%2};" : "=l"(r) : "f"(lo), "f"(hi)); return r;
}
__device__ __forceinline__ float2 unpack2(u64 v) {
    float2 r; asm("mov.b64 {%0,%1}, %2;" : "=f"(r.x), "=f"(r.y) : "l"(v)); return r;
}
__device__ __forceinline__ u64 ffma2(u64 a, u64 b, u64 c) {
    u64 d; asm("fma.rn.f32x2 %0, %1, %2, %3;" : "=l"(d) : "l"(a), "l"(b), "l"(c)); return d;
}
__device__ __forceinline__ float ex2f(float x) {
    float r; asm("ex2.approx.ftz.f32 %0, %1;" : "=f"(r) : "f"(x)); return r;
}

#define LOG2E 1.4426950408889634f

// Scratch (allocation-free rule: __device__ globals)
__device__ float d_theta[BATCH * HWDIM * CT];            // [b][n][8]
__device__ float d_phi  [BATCH * MDIM  * CT];            // [b][m][8]
__device__ float d_gbuf [BATCH * MDIM  * CG];            // [b][m][32]
__device__ float d_part [BATCH * MSPLIT * CG * HWDIM];   // [b][s][k][n]
__device__ float d_psum [BATCH * MSPLIT * HWDIM];        // [b][s][n]

// ---------------------------------------------------------------------------
// Kernel A: 1x1 projections + fused 2x2 maxpool for phi/g. FFMA2 everywhere.
// One thread per pooled pixel. grid (8,16), block 128.
// Weights in smem as channel-PAIRS: w2[c][j] = {w[2j][c], w[2j+1][c]}.
// ---------------------------------------------------------------------------
__global__ __launch_bounds__(128) void proj_kernel(
    const float* __restrict__ x,
    const float* __restrict__ wt,
    const float* __restrict__ wp,
    const float* __restrict__ wg)
{
    __shared__ u64 s_wt2[CDIM * 4];
    __shared__ u64 s_wp2[CDIM * 4];
    __shared__ u64 s_wg2[CDIM * 16];
    int tid = threadIdx.x;
    for (int i = tid; i < CDIM * 4; i += 128) {
        int c = i >> 2, j = i & 3;
        s_wt2[i] = pack2(wt[(2 * j) * CDIM + c], wt[(2 * j + 1) * CDIM + c]);
        s_wp2[i] = pack2(wp[(2 * j) * CDIM + c], wp[(2 * j + 1) * CDIM + c]);
    }
    for (int i = tid; i < CDIM * 16; i += 128) {
        int c = i >> 4, j = i & 15;
        s_wg2[i] = pack2(wg[(2 * j) * CDIM + c], wg[(2 * j + 1) * CDIM + c]);
    }
    __syncthreads();

    int b  = blockIdx.y;
    int pp = blockIdx.x * 128 + tid;       // pooled pixel 0..1023
    int py = pp >> 5, px = pp & 31;
    const float* xb = x + (size_t)b * CDIM * HWDIM;

    float phi_acc[CT], g_acc[CG];
#pragma unroll
    for (int o = 0; o < CT; o++) phi_acc[o] = -3.0e38f;
#pragma unroll
    for (int o = 0; o < CG; o++) g_acc[o] = -3.0e38f;

#pragma unroll
    for (int d = 0; d < 4; d++) {
        int dy = d >> 1, dx = d & 1;
        int pix = (2 * py + dy) * 64 + (2 * px + dx);
        u64 th2[4], ph2[4], gg2[16];
#pragma unroll
        for (int j = 0; j < 4; j++) { th2[j] = 0ull; ph2[j] = 0ull; }
#pragma unroll
        for (int j = 0; j < 16; j++) gg2[j] = 0ull;

#pragma unroll 8
        for (int c = 0; c < CDIM; c++) {
            float xc = xb[(size_t)c * HWDIM + pix];
            u64 x2 = pack2(xc, xc);
#pragma unroll
            for (int j = 0; j < 4; j++) {
                th2[j] = ffma2(s_wt2[c * 4 + j], x2, th2[j]);
                ph2[j] = ffma2(s_wp2[c * 4 + j], x2, ph2[j]);
            }
#pragma unroll
            for (int j = 0; j < 16; j++)
                gg2[j] = ffma2(s_wg2[c * 16 + j], x2, gg2[j]);
        }

        float2* tp = (float2*)&d_theta[((size_t)b * HWDIM + pix) * CT];
#pragma unroll
        for (int j = 0; j < 4; j++) {
            float2 v = unpack2(th2[j]);
            tp[j] = v;
            float2 p = unpack2(ph2[j]);
            phi_acc[2 * j]     = fmaxf(phi_acc[2 * j],     p.x);
            phi_acc[2 * j + 1] = fmaxf(phi_acc[2 * j + 1], p.y);
        }
#pragma unroll
        for (int j = 0; j < 16; j++) {
            float2 gv = unpack2(gg2[j]);
            g_acc[2 * j]     = fmaxf(g_acc[2 * j],     gv.x);
            g_acc[2 * j + 1] = fmaxf(g_acc[2 * j + 1], gv.y);
        }
    }

    float* pph = &d_phi[((size_t)b * MDIM + pp) * CT];
#pragma unroll
    for (int o = 0; o < CT; o++) pph[o] = phi_acc[o];
    float* pg = &d_gbuf[((size_t)b * MDIM + pp) * CG];
#pragma unroll
    for (int o = 0; o < CG; o++) pg[o] = g_acc[o];
}

// ---------------------------------------------------------------------------
// Kernel B: fused attention over HALF the keys (msplit partial softmax).
// grid (16 qtile, 2 split, 16 batch), 256 threads, smem 80KB -> 2 CTAs/SM.
// theta pre-scaled by log2e; ex2.approx; fixed shift cancels at combine.
// All inner-loop smem reads are warp-broadcasts. FFMA2 for score + value acc.
// ---------------------------------------------------------------------------
__global__ __launch_bounds__(256, 2) void attn_kernel(void)
{
    extern __shared__ u64 smem[];
    u64* s_phi = smem;                 // [512][4]  pairs of phi channels
    u64* s_g   = smem + MHALF * 4;     // [512][16] pairs of g channels

    int tid = threadIdx.x;
    int qt  = blockIdx.x;
    int sp  = blockIdx.y;
    int b   = blockIdx.z;
    int m0  = sp * MHALF;

    {   // cooperative smem fill (float4)
        const float4* sph = (const float4*)&d_phi[((size_t)b * MDIM + m0) * CT];
        float4* dph = (float4*)s_phi;
        for (int i = tid; i < MHALF * CT / 4; i += 256) dph[i] = sph[i];
        const float4* sg = (const float4*)&d_gbuf[((size_t)b * MDIM + m0) * CG];
        float4* dg = (float4*)s_g;
        for (int i = tid; i < MHALF * CG / 4; i += 256) dg[i] = sg[i];
    }
    __syncthreads();

    int n = qt * 256 + tid;
    u64 t2[4];
    {
        const float4* thp = (const float4*)&d_theta[((size_t)b * HWDIM + n) * CT];
        float4 t0 = thp[0], t1 = thp[1];
        t2[0] = pack2(t0.x * LOG2E, t0.y * LOG2E);
        t2[1] = pack2(t0.z * LOG2E, t0.w * LOG2E);
        t2[2] = pack2(t1.x * LOG2E, t1.y * LOG2E);
        t2[3] = pack2(t1.z * LOG2E, t1.w * LOG2E);
    }
    const u64 s_init = pack2(-12.0f * LOG2E, 0.0f);   // uniform shift, cancels

    float sum = 0.0f;
    u64 acc[16];
#pragma unroll
    for (int k = 0; k < 16; k++) acc[k] = 0ull;

#pragma unroll 2
    for (int m = 0; m < MHALF; m++) {
        const ulonglong2* pp = (const ulonglong2*)(s_phi + m * 4);
        ulonglong2 pa = pp[0], pb = pp[1];
        u64 s2 = ffma2(t2[0], pa.x, s_init);
        s2 = ffma2(t2[1], pa.y, s2);
        s2 = ffma2(t2[2], pb.x, s2);
        s2 = ffma2(t2[3], pb.y, s2);
        float2 sv = unpack2(s2);
        float e = ex2f(sv.x + sv.y);
        sum += e;
        u64 e2 = pack2(e, e);
        const ulonglong2* gp = (const ulonglong2*)(s_g + m * 16);
#pragma unroll
        for (int q = 0; q < 8; q++) {
            ulonglong2 gv = gp[q];
            acc[2 * q]     = ffma2(e2, gv.x, acc[2 * q]);
            acc[2 * q + 1] = ffma2(e2, gv.y, acc[2 * q + 1]);
        }
    }

    // write unnormalized partials, [b][s][k][n] for coalescing
    float* pb_ = &d_part[(((size_t)b * MSPLIT + sp) * CG) * HWDIM + n];
#pragma unroll
    for (int j = 0; j < 16; j++) {
        float2 v = unpack2(acc[j]);
        pb_[(size_t)(2 * j) * HWDIM]     = v.x;
        pb_[(size_t)(2 * j + 1) * HWDIM] = v.y;
    }
    d_psum[((size_t)b * MSPLIT + sp) * HWDIM + n] = sum;
}

// ---------------------------------------------------------------------------
// Kernel C: combine partials, normalize, w_o GEMV, gamma * o + x.
// grid (16, 16), 256 threads. One thread per query.
// ---------------------------------------------------------------------------
__global__ __launch_bounds__(256) void combine_kernel(
    const float* __restrict__ x,
    const float* __restrict__ wo,
    const float* __restrict__ gamma,
    float* __restrict__ out)
{
    __shared__ u64 s_wo2[CDIM * 16];   // pairs over k: {wo[c][2j], wo[c][2j+1]}
    int tid = threadIdx.x;
    for (int i = tid; i < CDIM * 16; i += 256) {
        int c = i >> 4, j = i & 15;
        s_wo2[i] = pack2(wo[c * CG + 2 * j], wo[c * CG + 2 * j + 1]);
    }
    __syncthreads();

    int b = blockIdx.y;
    int n = blockIdx.x * 256 + tid;

    const float* p0 = &d_part[(((size_t)b * MSPLIT + 0) * CG) * HWDIM + n];
    const float* p1 = &d_part[(((size_t)b * MSPLIT + 1) * CG) * HWDIM + n];
    float s0 = d_psum[((size_t)b * MSPLIT + 0) * HWDIM + n];
    float s1 = d_psum[((size_t)b * MSPLIT + 1) * HWDIM + n];
    float inv = 1.0f / (s0 + s1);

    u64 o2[16];
#pragma unroll
    for (int j = 0; j < 16; j++) {
        float a0 = (p0[(size_t)(2 * j) * HWDIM]     + p1[(size_t)(2 * j) * HWDIM])     * inv;
        float a1 = (p0[(size_t)(2 * j + 1) * HWDIM] + p1[(size_t)(2 * j + 1) * HWDIM]) * inv;
        o2[j] = pack2(a0, a1);
    }

    float gm = *gamma;
    const float* xb = x   + (size_t)b * CDIM * HWDIM + n;
    float*       ob = out + (size_t)b * CDIM * HWDIM + n;
#pragma unroll
    for (int c = 0; c < CDIM; c++) {
        u64 v2 = 0ull;
#pragma unroll
        for (int j = 0; j < 16; j++) v2 = ffma2(s_wo2[c * 16 + j], o2[j], v2);
        float2 v = unpack2(v2);
        ob[(size_t)c * HWDIM] = fmaf(gm, v.x + v.y, xb[(size_t)c * HWDIM]);
    }
}

// ---------------------------------------------------------------------------
extern "C" void kernel_launch(void* const* d_in, const int* in_sizes, int n_in,
                              void* d_out, int out_size)
{
    const float* x  = (const float*)d_in[0];
    const float* wt = (const float*)d_in[1];
    const float* wp = (const float*)d_in[2];
    const float* wg = (const float*)d_in[3];
    const float* wo = (const float*)d_in[4];
    const float* gm = (const float*)d_in[5];
    float* out = (float*)d_out;

    proj_kernel<<<dim3(8, BATCH), 128>>>(x, wt, wp, wg);

    int smem_bytes = (MHALF * 4 + MHALF * 16) * (int)sizeof(u64);   // 81920
    cudaFuncSetAttribute(attn_kernel, cudaFuncAttributeMaxDynamicSharedMemorySize,
                         smem_bytes);
    attn_kernel<<<dim3(HWDIM / 256, MSPLIT, BATCH), 256, smem_bytes>>>();

    combine_kernel<<<dim3(HWDIM / 256, BATCH), 256>>>(x, wo, gm, out);
}

// round 4
// speedup vs baseline: 1.6287x; 1.3144x over previous
#include <cuda_runtime.h>

// SelfAttn: B=16, C=64, H=W=64. theta/phi: 8 ch, g: 32 ch.
// phi,g maxpooled 2x2 -> M=1024 keys. HW=4096 queries.

#define BATCH 16
#define CDIM  64
#define HWDIM 4096
#define MDIM  1024
#define CT    8
#define CG    32
#define MSPLIT 2
#define MHALF (MDIM / MSPLIT)   // 512

typedef unsigned long long u64;

__device__ __forceinline__ u64 pack2(float lo, float hi) {
    u64 r; asm("mov.b64 %0, {%1,%2};" : "=l"(r) : "f"(lo), "f"(hi)); return r;
}
__device__ __forceinline__ float2 unpack2(u64 v) {
    float2 r; asm("mov.b64 {%0,%1}, %2;" : "=f"(r.x), "=f"(r.y) : "l"(v)); return r;
}
__device__ __forceinline__ u64 ffma2(u64 a, u64 b, u64 c) {
    u64 d; asm("fma.rn.f32x2 %0, %1, %2, %3;" : "=l"(d) : "l"(a), "l"(b), "l"(c)); return d;
}
__device__ __forceinline__ float ex2f(float x) {
    float r; asm("ex2.approx.ftz.f32 %0, %1;" : "=f"(r) : "f"(x)); return r;
}

#define LOG2E 1.4426950408889634f

// Scratch (allocation-free rule: __device__ globals)
__device__ float d_theta[BATCH * HWDIM * CT];            // [b][n][8]
__device__ float d_phi  [BATCH * MDIM  * CT];            // [b][m][8]
__device__ float d_gbuf [BATCH * MDIM  * CG];            // [b][m][32]
__device__ float d_part [BATCH * MSPLIT * CG * HWDIM];   // [b][s][k][n]
__device__ float d_psum [BATCH * MSPLIT * HWDIM];        // [b][s][n]

// ---------------------------------------------------------------------------
// Kernel A: 1x1 projections + fused 2x2 maxpool for phi/g.
// One thread per VERTICAL pixel pair (rows 2py, 2py+1 at column x):
//   - x loads fully coalesced (consecutive lanes -> consecutive columns)
//   - vertical max in-thread, horizontal max via shfl_xor(1)
//   - weights in smem as channel-pairs, fetched as LDS.128
// grid (16, 16), block 128.  48 FFMA2 per c-iter vs 12 LDS.128 -> FMA-bound.
// ---------------------------------------------------------------------------
__global__ __launch_bounds__(128) void proj_kernel(
    const float* __restrict__ x,
    const float* __restrict__ wt,
    const float* __restrict__ wp,
    const float* __restrict__ wg)
{
    __shared__ __align__(16) u64 s_wt2[CDIM * 4];
    __shared__ __align__(16) u64 s_wp2[CDIM * 4];
    __shared__ __align__(16) u64 s_wg2[CDIM * 16];
    int tid = threadIdx.x;
    for (int i = tid; i < CDIM * 4; i += 128) {
        int c = i >> 2, j = i & 3;
        s_wt2[i] = pack2(wt[(2 * j) * CDIM + c], wt[(2 * j + 1) * CDIM + c]);
        s_wp2[i] = pack2(wp[(2 * j) * CDIM + c], wp[(2 * j + 1) * CDIM + c]);
    }
    for (int i = tid; i < CDIM * 16; i += 128) {
        int c = i >> 4, j = i & 15;
        s_wg2[i] = pack2(wg[(2 * j) * CDIM + c], wg[(2 * j + 1) * CDIM + c]);
    }
    __syncthreads();

    int b  = blockIdx.y;
    int gt = blockIdx.x * 128 + tid;     // 0..2047
    int py = gt >> 6;                    // row-pair 0..31
    int xc = gt & 63;                    // column 0..63
    int p0 = (2 * py) * 64 + xc;
    int p1 = p0 + 64;
    const float* xb = x + (size_t)b * CDIM * HWDIM;

    u64 th0[4], th1[4], ph0[4], ph1[4], g0[16], g1[16];
#pragma unroll
    for (int j = 0; j < 4; j++) { th0[j] = th1[j] = ph0[j] = ph1[j] = 0ull; }
#pragma unroll
    for (int j = 0; j < 16; j++) { g0[j] = g1[j] = 0ull; }

#pragma unroll 4
    for (int c = 0; c < CDIM; c++) {
        float a0 = xb[(size_t)c * HWDIM + p0];
        float a1 = xb[(size_t)c * HWDIM + p1];
        u64 xa = pack2(a0, a0);
        u64 xbv = pack2(a1, a1);
        const ulonglong2* wtp = (const ulonglong2*)(s_wt2 + c * 4);
        const ulonglong2* wpp = (const ulonglong2*)(s_wp2 + c * 4);
        const ulonglong2* wgp = (const ulonglong2*)(s_wg2 + c * 16);
#pragma unroll
        for (int jj = 0; jj < 2; jj++) {
            ulonglong2 w = wtp[jj];
            th0[2 * jj]     = ffma2(w.x, xa,  th0[2 * jj]);
            th1[2 * jj]     = ffma2(w.x, xbv, th1[2 * jj]);
            th0[2 * jj + 1] = ffma2(w.y, xa,  th0[2 * jj + 1]);
            th1[2 * jj + 1] = ffma2(w.y, xbv, th1[2 * jj + 1]);
            ulonglong2 v = wpp[jj];
            ph0[2 * jj]     = ffma2(v.x, xa,  ph0[2 * jj]);
            ph1[2 * jj]     = ffma2(v.x, xbv, ph1[2 * jj]);
            ph0[2 * jj + 1] = ffma2(v.y, xa,  ph0[2 * jj + 1]);
            ph1[2 * jj + 1] = ffma2(v.y, xbv, ph1[2 * jj + 1]);
        }
#pragma unroll
        for (int jj = 0; jj < 8; jj++) {
            ulonglong2 w = wgp[jj];
            g0[2 * jj]     = ffma2(w.x, xa,  g0[2 * jj]);
            g1[2 * jj]     = ffma2(w.x, xbv, g1[2 * jj]);
            g0[2 * jj + 1] = ffma2(w.y, xa,  g0[2 * jj + 1]);
            g1[2 * jj + 1] = ffma2(w.y, xbv, g1[2 * jj + 1]);
        }
    }

    // theta: both pixels, 2 x STG.128 each
    {
        ulonglong2* t0 = (ulonglong2*)&d_theta[((size_t)b * HWDIM + p0) * CT];
        t0[0] = make_ulonglong2(th0[0], th0[1]);
        t0[1] = make_ulonglong2(th0[2], th0[3]);
        ulonglong2* t1 = (ulonglong2*)&d_theta[((size_t)b * HWDIM + p1) * CT];
        t1[0] = make_ulonglong2(th1[0], th1[1]);
        t1[1] = make_ulonglong2(th1[2], th1[3]);
    }

    // pool: vertical max (in-thread) then horizontal (shfl_xor 1)
    float pphv[CT], pgv[CG];
#pragma unroll
    for (int j = 0; j < 4; j++) {
        float2 a = unpack2(ph0[j]), bb = unpack2(ph1[j]);
        pphv[2 * j]     = fmaxf(a.x, bb.x);
        pphv[2 * j + 1] = fmaxf(a.y, bb.y);
    }
#pragma unroll
    for (int j = 0; j < 16; j++) {
        float2 a = unpack2(g0[j]), bb = unpack2(g1[j]);
        pgv[2 * j]     = fmaxf(a.x, bb.x);
        pgv[2 * j + 1] = fmaxf(a.y, bb.y);
    }
#pragma unroll
    for (int o = 0; o < CT; o++)
        pphv[o] = fmaxf(pphv[o], __shfl_xor_sync(0xffffffffu, pphv[o], 1));
#pragma unroll
    for (int o = 0; o < CG; o++)
        pgv[o] = fmaxf(pgv[o], __shfl_xor_sync(0xffffffffu, pgv[o], 1));

    if (!(xc & 1)) {
        int pp = py * 32 + (xc >> 1);
        u64* pph = (u64*)&d_phi[((size_t)b * MDIM + pp) * CT];
#pragma unroll
        for (int j = 0; j < 4; j++) pph[j] = pack2(pphv[2 * j], pphv[2 * j + 1]);
        u64* pg = (u64*)&d_gbuf[((size_t)b * MDIM + pp) * CG];
#pragma unroll
        for (int j = 0; j < 16; j++) pg[j] = pack2(pgv[2 * j], pgv[2 * j + 1]);
    }
}

// ---------------------------------------------------------------------------
// Kernel B: fused attention over half the keys, TWO queries per thread.
// grid (8 qtile, 2 split, 16 batch), 256 threads, smem 80KB -> 2 CTAs/SM.
// Per m-iter: 10 LDS.128 amortized over 2 queries; 40 FFMA2 -> FMA-pipe-bound.
// theta pre-scaled by log2e; ex2.approx; fixed shift cancels at combine.
// ---------------------------------------------------------------------------
__global__ __launch_bounds__(256, 2) void attn_kernel(void)
{
    extern __shared__ u64 smem[];
    u64* s_phi = smem;                 // [512][4]  pairs of phi channels
    u64* s_g   = smem + MHALF * 4;     // [512][16] pairs of g channels

    int tid = threadIdx.x;
    int qt  = blockIdx.x;
    int sp  = blockIdx.y;
    int b   = blockIdx.z;
    int m0  = sp * MHALF;

    {   // cooperative smem fill (float4)
        const float4* sph = (const float4*)&d_phi[((size_t)b * MDIM + m0) * CT];
        float4* dph = (float4*)s_phi;
        for (int i = tid; i < MHALF * CT / 4; i += 256) dph[i] = sph[i];
        const float4* sg = (const float4*)&d_gbuf[((size_t)b * MDIM + m0) * CG];
        float4* dg = (float4*)s_g;
        for (int i = tid; i < MHALF * CG / 4; i += 256) dg[i] = sg[i];
    }
    __syncthreads();

    int n0 = qt * 512 + tid;
    int n1 = n0 + 256;
    u64 ta[4], tb[4];
    {
        const float4* thp = (const float4*)&d_theta[((size_t)b * HWDIM + n0) * CT];
        float4 t0 = thp[0], t1 = thp[1];
        ta[0] = pack2(t0.x * LOG2E, t0.y * LOG2E);
        ta[1] = pack2(t0.z * LOG2E, t0.w * LOG2E);
        ta[2] = pack2(t1.x * LOG2E, t1.y * LOG2E);
        ta[3] = pack2(t1.z * LOG2E, t1.w * LOG2E);
        const float4* thq = (const float4*)&d_theta[((size_t)b * HWDIM + n1) * CT];
        float4 u0 = thq[0], u1 = thq[1];
        tb[0] = pack2(u0.x * LOG2E, u0.y * LOG2E);
        tb[1] = pack2(u0.z * LOG2E, u0.w * LOG2E);
        tb[2] = pack2(u1.x * LOG2E, u1.y * LOG2E);
        tb[3] = pack2(u1.z * LOG2E, u1.w * LOG2E);
    }
    const u64 s_init = pack2(-12.0f * LOG2E, 0.0f);   // uniform shift, cancels

    float sum0 = 0.0f, sum1 = 0.0f;
    u64 acc0[16], acc1[16];
#pragma unroll
    for (int k = 0; k < 16; k++) { acc0[k] = 0ull; acc1[k] = 0ull; }

#pragma unroll 2
    for (int m = 0; m < MHALF; m++) {
        const ulonglong2* pp = (const ulonglong2*)(s_phi + m * 4);
        ulonglong2 pa = pp[0], pb = pp[1];
        u64 s0 = ffma2(ta[0], pa.x, s_init);
        s0 = ffma2(ta[1], pa.y, s0);
        s0 = ffma2(ta[2], pb.x, s0);
        s0 = ffma2(ta[3], pb.y, s0);
        u64 s1 = ffma2(tb[0], pa.x, s_init);
        s1 = ffma2(tb[1], pa.y, s1);
        s1 = ffma2(tb[2], pb.x, s1);
        s1 = ffma2(tb[3], pb.y, s1);
        float2 v0 = unpack2(s0);
        float2 v1 = unpack2(s1);
        float e0 = ex2f(v0.x + v0.y);
        float e1 = ex2f(v1.x + v1.y);
        sum0 += e0;
        sum1 += e1;
        u64 e02 = pack2(e0, e0);
        u64 e12 = pack2(e1, e1);
        const ulonglong2* gp = (const ulonglong2*)(s_g + m * 16);
#pragma unroll
        for (int q = 0; q < 8; q++) {
            ulonglong2 gv = gp[q];
            acc0[2 * q]     = ffma2(e02, gv.x, acc0[2 * q]);
            acc0[2 * q + 1] = ffma2(e02, gv.y, acc0[2 * q + 1]);
            acc1[2 * q]     = ffma2(e12, gv.x, acc1[2 * q]);
            acc1[2 * q + 1] = ffma2(e12, gv.y, acc1[2 * q + 1]);
        }
    }

    // write unnormalized partials, [b][s][k][n] for coalescing
    float* pbase = &d_part[(((size_t)b * MSPLIT + sp) * CG) * HWDIM];
#pragma unroll
    for (int j = 0; j < 16; j++) {
        float2 a = unpack2(acc0[j]);
        pbase[(size_t)(2 * j) * HWDIM + n0]     = a.x;
        pbase[(size_t)(2 * j + 1) * HWDIM + n0] = a.y;
        float2 c = unpack2(acc1[j]);
        pbase[(size_t)(2 * j) * HWDIM + n1]     = c.x;
        pbase[(size_t)(2 * j + 1) * HWDIM + n1] = c.y;
    }
    d_psum[((size_t)b * MSPLIT + sp) * HWDIM + n0] = sum0;
    d_psum[((size_t)b * MSPLIT + sp) * HWDIM + n1] = sum1;
}

// ---------------------------------------------------------------------------
// Kernel C: combine partials, normalize, w_o GEMV, gamma * o + x.
// grid (16, 16), 256 threads. One thread per query.
// ---------------------------------------------------------------------------
__global__ __launch_bounds__(256) void combine_kernel(
    const float* __restrict__ x,
    const float* __restrict__ wo,
    const float* __restrict__ gamma,
    float* __restrict__ out)
{
    __shared__ u64 s_wo2[CDIM * 16];   // pairs over k: {wo[c][2j], wo[c][2j+1]}
    int tid = threadIdx.x;
    for (int i = tid; i < CDIM * 16; i += 256) {
        int c = i >> 4, j = i & 15;
        s_wo2[i] = pack2(wo[c * CG + 2 * j], wo[c * CG + 2 * j + 1]);
    }
    __syncthreads();

    int b = blockIdx.y;
    int n = blockIdx.x * 256 + tid;

    const float* p0 = &d_part[(((size_t)b * MSPLIT + 0) * CG) * HWDIM + n];
    const float* p1 = &d_part[(((size_t)b * MSPLIT + 1) * CG) * HWDIM + n];
    float s0 = d_psum[((size_t)b * MSPLIT + 0) * HWDIM + n];
    float s1 = d_psum[((size_t)b * MSPLIT + 1) * HWDIM + n];
    float inv = 1.0f / (s0 + s1);

    u64 o2[16];
#pragma unroll
    for (int j = 0; j < 16; j++) {
        float a0 = (p0[(size_t)(2 * j) * HWDIM]     + p1[(size_t)(2 * j) * HWDIM])     * inv;
        float a1 = (p0[(size_t)(2 * j + 1) * HWDIM] + p1[(size_t)(2 * j + 1) * HWDIM]) * inv;
        o2[j] = pack2(a0, a1);
    }

    float gm = *gamma;
    const float* xb = x   + (size_t)b * CDIM * HWDIM + n;
    float*       ob = out + (size_t)b * CDIM * HWDIM + n;
#pragma unroll
    for (int c = 0; c < CDIM; c++) {
        u64 v2 = 0ull;
#pragma unroll
        for (int j = 0; j < 16; j++) v2 = ffma2(s_wo2[c * 16 + j], o2[j], v2);
        float2 v = unpack2(v2);
        ob[(size_t)c * HWDIM] = fmaf(gm, v.x + v.y, xb[(size_t)c * HWDIM]);
    }
}

// ---------------------------------------------------------------------------
extern "C" void kernel_launch(void* const* d_in, const int* in_sizes, int n_in,
                              void* d_out, int out_size)
{
    const float* x  = (const float*)d_in[0];
    const float* wt = (const float*)d_in[1];
    const float* wp = (const float*)d_in[2];
    const float* wg = (const float*)d_in[3];
    const float* wo = (const float*)d_in[4];
    const float* gm = (const float*)d_in[5];
    float* out = (float*)d_out;

    proj_kernel<<<dim3(16, BATCH), 128>>>(x, wt, wp, wg);

    int smem_bytes = (MHALF * 4 + MHALF * 16) * (int)sizeof(u64);   // 81920
    cudaFuncSetAttribute(attn_kernel, cudaFuncAttributeMaxDynamicSharedMemorySize,
                         smem_bytes);
    attn_kernel<<<dim3(HWDIM / 512, MSPLIT, BATCH), 256, smem_bytes>>>();

    combine_kernel<<<dim3(HWDIM / 256, BATCH), 256>>>(x, wo, gm, out);
}